// round 1
// baseline (speedup 1.0000x reference)
#include <cuda_runtime.h>
#include <math.h>

#define NTOK  65536
#define IN_F  64
#define OUT_F 64
#define RAD_F 32
#define ANG_F 16
#define HID   64

#define TOK_TILE 64
#define THREADS  256

// Scratch (device-global: allocation-free per harness rules)
__device__ float g_h[(size_t)NTOK * HID];     // silu(radial@W1+b1)
__device__ float g_ang[(size_t)NTOK * OUT_F]; // angular@Wa+ba

// ---------------------------------------------------------------------------
// Precompute kernel: h and ang for 4 tokens per CTA (256 threads).
// ---------------------------------------------------------------------------
__global__ void tp_precompute_kernel(const float* __restrict__ radial,
                                     const float* __restrict__ angular,
                                     const float* __restrict__ W1,
                                     const float* __restrict__ b1,
                                     const float* __restrict__ Wa,
                                     const float* __restrict__ ba)
{
    __shared__ float sW1[RAD_F * HID];
    __shared__ float sWa[ANG_F * OUT_F];
    __shared__ float sb1[HID];
    __shared__ float sba[OUT_F];
    __shared__ float srad[4][RAD_F];
    __shared__ float sang[4][ANG_F];

    const int tid = threadIdx.x;
    const int n0  = blockIdx.x * 4;

    for (int idx = tid; idx < RAD_F * HID; idx += THREADS) sW1[idx] = W1[idx];
    for (int idx = tid; idx < ANG_F * OUT_F; idx += THREADS) sWa[idx] = Wa[idx];
    if (tid < HID)   sb1[tid] = b1[tid];
    if (tid < OUT_F) sba[tid] = ba[tid];
    for (int idx = tid; idx < 4 * RAD_F; idx += THREADS) {
        int t = idx / RAD_F, r = idx % RAD_F;
        srad[t][r] = radial[(size_t)(n0 + t) * RAD_F + r];
    }
    for (int idx = tid; idx < 4 * ANG_F; idx += THREADS) {
        int t = idx / ANG_F, r = idx % ANG_F;
        sang[t][r] = angular[(size_t)(n0 + t) * ANG_F + r];
    }
    __syncthreads();

    const int t = tid >> 6;   // 0..3 token within tile
    const int j = tid & 63;   // 0..63 feature

    float acch = sb1[j];
#pragma unroll
    for (int r = 0; r < RAD_F; r++) acch = fmaf(srad[t][r], sW1[r * HID + j], acch);
    // silu(x) = x * sigmoid(x) = x / (1 + e^-x)
    float hval = acch / (1.0f + expf(-acch));
    g_h[(size_t)(n0 + t) * HID + j] = hval;

    float acca = sba[j];
#pragma unroll
    for (int r = 0; r < ANG_F; r++) acca = fmaf(sang[t][r], sWa[r * OUT_F + j], acca);
    g_ang[(size_t)(n0 + t) * OUT_F + j] = acca;
}

// ---------------------------------------------------------------------------
// Helpers
// ---------------------------------------------------------------------------
__device__ __forceinline__ void cp_async16(float* smem_dst, const float* gsrc) {
    unsigned sm = (unsigned)__cvta_generic_to_shared(smem_dst);
    asm volatile("cp.async.cg.shared.global [%0], [%1], 16;" :: "r"(sm), "l"(gsrc));
}
__device__ __forceinline__ unsigned long long pack_dup(float c) {
    unsigned long long r;
    asm("mov.b64 %0, {%1, %1};" : "=l"(r) : "f"(c));
    return r;
}
__device__ __forceinline__ void ffma2(unsigned long long& acc,
                                      unsigned long long a,
                                      unsigned long long b) {
    asm("fma.rn.f32x2 %0, %1, %2, %0;" : "+l"(acc) : "l"(a), "l"(b));
}

// Dynamic smem layout (floats):
//   f_s : TOK_TILE * 65        (padded to kill bank conflicts)
//   h_s : TOK_TILE * 65
//   w_s : 2 * HID*OUT_F        (double-buffered W2 k-slab / b2 slab)
#define FS_STRIDE 65
#define SMEM_FLOATS (2 * TOK_TILE * FS_STRIDE + 2 * HID * OUT_F)

// ---------------------------------------------------------------------------
// Main kernel: 64 tokens/CTA. Thread = 4 tokens x 4 outputs.
// Contraction: out[n,o] = sum_k sum_i h[n,k]*f[n,i]*W2[k,i*64+o]  (+ b2 pass)
// ---------------------------------------------------------------------------
__global__ __launch_bounds__(THREADS, 2)
void tp_main_kernel(const float* __restrict__ features,
                    const float* __restrict__ W2,
                    const float* __restrict__ b2,
                    float* __restrict__ out)
{
    extern __shared__ float smem[];
    float* f_s = smem;
    float* h_s = smem + TOK_TILE * FS_STRIDE;
    float* w_s = smem + 2 * TOK_TILE * FS_STRIDE;  // [2][4096]

    const int tid = threadIdx.x;
    const int n0  = blockIdx.x * TOK_TILE;

    // Stage f and h tiles (coalesced global reads)
    for (int idx = tid; idx < TOK_TILE * IN_F; idx += THREADS) {
        int t = idx >> 6, i = idx & 63;
        f_s[t * FS_STRIDE + i] = features[(size_t)(n0 + t) * IN_F + i];
        h_s[t * FS_STRIDE + i] = g_h[(size_t)(n0 + t) * HID + i];
    }

    // Slab pipeline: slabs 0..HID-1 are W2[k], slab HID is b2 (coefficient 1).
    auto issue_slab = [&](int k) {
        const float* src = (k < HID) ? (W2 + (size_t)k * (IN_F * OUT_F)) : b2;
        float* dst = w_s + (k & 1) * (HID * OUT_F);
        for (int v = tid; v < (IN_F * OUT_F) / 4; v += THREADS)
            cp_async16(dst + v * 4, src + v * 4);
        asm volatile("cp.async.commit_group;");
    };
    issue_slab(0);
    issue_slab(1);

    const int tt  = tid >> 4;      // 0..15 -> tokens tt*4 .. tt*4+3
    const int ot  = tid & 15;      // 0..15 -> outputs ot*4 .. ot*4+3
    const int tok = tt * 4;

    unsigned long long acc[4][2];
#pragma unroll
    for (int j = 0; j < 4; j++) { acc[j][0] = 0ull; acc[j][1] = 0ull; }

    for (int k = 0; k <= HID; k++) {
        if (k < HID) asm volatile("cp.async.wait_group 1;");
        else         asm volatile("cp.async.wait_group 0;");
        __syncthreads();  // slab k visible to all; also covers f_s/h_s on k==0

        const float* wbuf = w_s + (k & 1) * (HID * OUT_F);

        float ht0, ht1, ht2, ht3;
        if (k < HID) {
            ht0 = h_s[(tok + 0) * FS_STRIDE + k];
            ht1 = h_s[(tok + 1) * FS_STRIDE + k];
            ht2 = h_s[(tok + 2) * FS_STRIDE + k];
            ht3 = h_s[(tok + 3) * FS_STRIDE + k];
        } else {
            ht0 = ht1 = ht2 = ht3 = 1.0f;  // b2 pass: coefficient is f alone
        }

#pragma unroll 8
        for (int i = 0; i < IN_F; i++) {
            const ulonglong2 wv =
                *reinterpret_cast<const ulonglong2*>(&wbuf[i * OUT_F + ot * 4]);

            float c0 = ht0 * f_s[(tok + 0) * FS_STRIDE + i];
            float c1 = ht1 * f_s[(tok + 1) * FS_STRIDE + i];
            float c2 = ht2 * f_s[(tok + 2) * FS_STRIDE + i];
            float c3 = ht3 * f_s[(tok + 3) * FS_STRIDE + i];

            unsigned long long cp0 = pack_dup(c0);
            unsigned long long cp1 = pack_dup(c1);
            unsigned long long cp2 = pack_dup(c2);
            unsigned long long cp3 = pack_dup(c3);

            ffma2(acc[0][0], cp0, wv.x);  ffma2(acc[0][1], cp0, wv.y);
            ffma2(acc[1][0], cp1, wv.x);  ffma2(acc[1][1], cp1, wv.y);
            ffma2(acc[2][0], cp2, wv.x);  ffma2(acc[2][1], cp2, wv.y);
            ffma2(acc[3][0], cp3, wv.x);  ffma2(acc[3][1], cp3, wv.y);
        }

        __syncthreads();  // everyone done reading buf (k&1) before refill
        if (k + 2 <= HID) issue_slab(k + 2);
    }

    // Epilogue: multiply by ang, store.
#pragma unroll
    for (int j = 0; j < 4; j++) {
        const int n = n0 + tok + j;
#pragma unroll
        for (int p = 0; p < 2; p++) {
            float a0, a1;
            asm("mov.b64 {%0, %1}, %2;" : "=f"(a0), "=f"(a1) : "l"(acc[j][p]));
            const int o = ot * 4 + p * 2;
            float gg0 = g_ang[(size_t)n * OUT_F + o];
            float gg1 = g_ang[(size_t)n * OUT_F + o + 1];
            float2 r;
            r.x = a0 * gg0;
            r.y = a1 * gg1;
            *reinterpret_cast<float2*>(&out[(size_t)n * OUT_F + o]) = r;
        }
    }
}

// ---------------------------------------------------------------------------
// Launch
// ---------------------------------------------------------------------------
extern "C" void kernel_launch(void* const* d_in, const int* in_sizes, int n_in,
                              void* d_out, int out_size)
{
    const float* features = (const float*)d_in[0];
    const float* radial   = (const float*)d_in[1];
    const float* angular  = (const float*)d_in[2];
    const float* W1       = (const float*)d_in[3];
    const float* b1       = (const float*)d_in[4];
    const float* W2       = (const float*)d_in[5];
    const float* b2       = (const float*)d_in[6];
    const float* Wa       = (const float*)d_in[7];
    const float* ba       = (const float*)d_in[8];
    float* out = (float*)d_out;

    (void)in_sizes; (void)n_in; (void)out_size;

    const int smem_bytes = SMEM_FLOATS * (int)sizeof(float);
    cudaFuncSetAttribute(tp_main_kernel,
                         cudaFuncAttributeMaxDynamicSharedMemorySize, smem_bytes);

    tp_precompute_kernel<<<NTOK / 4, THREADS>>>(radial, angular, W1, b1, Wa, ba);
    tp_main_kernel<<<NTOK / TOK_TILE, THREADS, smem_bytes>>>(features, W2, b2, out);
}

// round 3
// speedup vs baseline: 2.6152x; 2.6152x over previous
#include <cuda_runtime.h>
#include <cuda_bf16.h>
#include <math.h>
#include <stdint.h>

#define NTOK  65536
#define IN_F  64
#define OUT_F 64
#define RAD_F 32
#define ANG_F 16
#define HID   64

#define TILE_M   128
#define NTILES   (NTOK / TILE_M)   // 512
#define THREADS  256

#define APITCH      144            // padded row: 72 bf16 (conflict-free ldmatrix)
#define A_TILE_HALF 18432          // 128 rows * 144 B
#define B_TILE_HALF 9216           // 64 rows * 144 B
#define B_SLOT      18432          // hi + lo halves

// ---------------------------------------------------------------------------
// Device-global scratch (allocation-free rule)
// ---------------------------------------------------------------------------
// A (= split h) per tile: [hi 18432 | lo 18432], rows m, cols k, 144B pitch
__device__ __align__(1024) uint8_t g_A[(size_t)NTILES * 2 * A_TILE_HALF];
// B (= W2 transposed per i): [i][hi 9216 | lo 9216], rows o, cols k, 144B pitch
__device__ __align__(1024) uint8_t g_W2t[(size_t)64 * B_SLOT];
// b2 tile: rows o, cols i, 144B pitch, [hi | lo]
__device__ __align__(1024) uint8_t g_b2t[B_SLOT];
__device__ float g_ang[(size_t)NTOK * OUT_F];

// ---------------------------------------------------------------------------
// Precompute 1: h = silu(radial@W1+b1) -> split bf16 padded tiles; ang fp32.
// ---------------------------------------------------------------------------
__global__ void tp_precompute(const float* __restrict__ radial,
                              const float* __restrict__ angular,
                              const float* __restrict__ W1,
                              const float* __restrict__ b1,
                              const float* __restrict__ Wa,
                              const float* __restrict__ ba)
{
    __shared__ float sW1[RAD_F * HID];
    __shared__ float sWa[ANG_F * OUT_F];
    __shared__ float sb1[HID];
    __shared__ float sba[OUT_F];
    __shared__ float srad[64][RAD_F + 1];
    __shared__ float sang[64][ANG_F + 1];

    const int tid = threadIdx.x;
    const int n0  = blockIdx.x * 64;

    for (int idx = tid; idx < RAD_F * HID; idx += THREADS) sW1[idx] = W1[idx];
    for (int idx = tid; idx < ANG_F * OUT_F; idx += THREADS) sWa[idx] = Wa[idx];
    if (tid < HID)   sb1[tid] = b1[tid];
    if (tid < OUT_F) sba[tid] = ba[tid];
    for (int idx = tid; idx < 64 * RAD_F; idx += THREADS) {
        int t = idx >> 5, r = idx & 31;
        srad[t][r] = radial[(size_t)(n0 + t) * RAD_F + r];
    }
    for (int idx = tid; idx < 64 * ANG_F; idx += THREADS) {
        int t = idx >> 4, r = idx & 15;
        sang[t][r] = angular[(size_t)(n0 + t) * ANG_F + r];
    }
    __syncthreads();

    const int j = tid & 63;
    for (int tt = tid >> 6; tt < 64; tt += 4) {
        const int n = n0 + tt;

        float acch = sb1[j];
#pragma unroll
        for (int r = 0; r < RAD_F; r++) acch = fmaf(srad[tt][r], sW1[r * HID + j], acch);
        float hval = acch / (1.0f + expf(-acch));

        __nv_bfloat16 hi = __float2bfloat16(hval);
        __nv_bfloat16 lo = __float2bfloat16(hval - __bfloat162float(hi));

        const int m    = n & (TILE_M - 1);
        const int tile = n >> 7;
        uint8_t* base = g_A + (size_t)tile * (2 * A_TILE_HALF) + m * APITCH + j * 2;
        *(__nv_bfloat16*)base                 = hi;
        *(__nv_bfloat16*)(base + A_TILE_HALF) = lo;

        float acca = sba[j];
#pragma unroll
        for (int r = 0; r < ANG_F; r++) acca = fmaf(sang[tt][r], sWa[r * OUT_F + j], acca);
        g_ang[(size_t)n * OUT_F + j] = acca;
    }
}

// ---------------------------------------------------------------------------
// Precompute 2: W2[k, i*64+o] -> B_i[o][k] split bf16, padded.
// ---------------------------------------------------------------------------
__global__ void tp_w2split(const float* __restrict__ W2)
{
    const int idx = blockIdx.x * THREADS + threadIdx.x;   // 0..262143
    const int k  = idx >> 12;
    const int io = idx & 4095;
    const int o  = io & 63;
    const int i  = io >> 6;

    float v = W2[idx];
    __nv_bfloat16 hi = __float2bfloat16(v);
    __nv_bfloat16 lo = __float2bfloat16(v - __bfloat162float(hi));

    uint8_t* base = g_W2t + (size_t)i * B_SLOT + o * APITCH + k * 2;
    *(__nv_bfloat16*)base                 = hi;
    *(__nv_bfloat16*)(base + B_TILE_HALF) = lo;
}

// Precompute 3: b2[i*64+o] -> tile [o][i] split bf16, padded.
__global__ void tp_b2split(const float* __restrict__ b2)
{
    const int idx = blockIdx.x * THREADS + threadIdx.x;   // 0..4095
    const int i = idx >> 6;
    const int o = idx & 63;
    float v = b2[idx];
    __nv_bfloat16 hi = __float2bfloat16(v);
    __nv_bfloat16 lo = __float2bfloat16(v - __bfloat162float(hi));
    uint8_t* base = g_b2t + o * APITCH + i * 2;
    *(__nv_bfloat16*)base                 = hi;
    *(__nv_bfloat16*)(base + B_TILE_HALF) = lo;
}

// ---------------------------------------------------------------------------
// PTX helpers (all baseline sm_80+ features)
// ---------------------------------------------------------------------------
__device__ __forceinline__ void cp16(uint32_t s, const void* g) {
    asm volatile("cp.async.cg.shared.global [%0], [%1], 16;" :: "r"(s), "l"(g));
}
__device__ __forceinline__ void ldsm_x4(uint32_t* r, uint32_t addr) {
    asm volatile("ldmatrix.sync.aligned.m8n8.x4.shared.b16 {%0,%1,%2,%3}, [%4];"
        : "=r"(r[0]), "=r"(r[1]), "=r"(r[2]), "=r"(r[3]) : "r"(addr));
}
__device__ __forceinline__ void mma_bf16(float* d, const uint32_t* a,
                                         uint32_t b0, uint32_t b1) {
    asm volatile(
        "mma.sync.aligned.m16n8k16.row.col.f32.bf16.bf16.f32 "
        "{%0,%1,%2,%3}, {%4,%5,%6,%7}, {%8,%9}, {%0,%1,%2,%3};"
        : "+f"(d[0]), "+f"(d[1]), "+f"(d[2]), "+f"(d[3])
        : "r"(a[0]), "r"(a[1]), "r"(a[2]), "r"(a[3]), "r"(b0), "r"(b1));
}

// ---------------------------------------------------------------------------
// SMEM layout (bytes)
// ---------------------------------------------------------------------------
#define SM_A    0u        // h tiles: hi | lo  (36864)
#define SM_F    36864u    // f tiles: hi | lo  (36864)
#define SM_B    73728u    // 2 streaming buffers of B_SLOT (36864)
#define SM_B2   110592u   // b2 tile hi | lo (18432)
#define SM_FS   129024u   // f fp32 [128][68] (34816)
#define SMEM_BYTES 163840

// 3-pass split consume: D = Ahi*Bhi + Alo*Bhi + Ahi*Blo   (fp32 accum)
__device__ __forceinline__ void consume_slot(float D[8][4],
                                             const uint32_t Ah[4][4],
                                             const uint32_t Al[4][4],
                                             uint32_t bbase,
                                             uint32_t b_row, uint32_t b_kadd)
{
#pragma unroll
    for (int nt = 0; nt < 8; nt++)
#pragma unroll
        for (int j = 0; j < 4; j++) D[nt][j] = 0.0f;

#pragma unroll
    for (int ks = 0; ks < 4; ks++) {
        uint32_t bh[16];
#pragma unroll
        for (int g = 0; g < 4; g++)
            ldsm_x4(bh + 4 * g,
                    bbase + (g * 16 + b_row) * APITCH + ks * 32 + b_kadd);
#pragma unroll
        for (int nt = 0; nt < 8; nt++) {
            const uint32_t b0 = bh[(nt >> 1) * 4 + (nt & 1) * 2];
            const uint32_t b1 = bh[(nt >> 1) * 4 + (nt & 1) * 2 + 1];
            mma_bf16(D[nt], Ah[ks], b0, b1);
            mma_bf16(D[nt], Al[ks], b0, b1);
        }
        uint32_t bl[16];
#pragma unroll
        for (int g = 0; g < 4; g++)
            ldsm_x4(bl + 4 * g,
                    bbase + B_TILE_HALF + (g * 16 + b_row) * APITCH + ks * 32 + b_kadd);
#pragma unroll
        for (int nt = 0; nt < 8; nt++) {
            const uint32_t b0 = bl[(nt >> 1) * 4 + (nt & 1) * 2];
            const uint32_t b1 = bl[(nt >> 1) * 4 + (nt & 1) * 2 + 1];
            mma_bf16(D[nt], Ah[ks], b0, b1);
        }
    }
}

// ---------------------------------------------------------------------------
// Main kernel
// ---------------------------------------------------------------------------
__global__ __launch_bounds__(THREADS, 1)
void tp_main(const float* __restrict__ features, float* __restrict__ out)
{
    extern __shared__ __align__(1024) uint8_t smem[];
    const uint32_t sb = (uint32_t)__cvta_generic_to_shared(smem);
    const int tid  = threadIdx.x;
    const int lane = tid & 31;
    const int warp = tid >> 5;
    const int tile = blockIdx.x;
    const int n0   = tile * TILE_M;

    // ---- stage async copies: A tile, b2, B slots 0 & 1 ----
    {
        const uint8_t* srcA = g_A + (size_t)tile * (2 * A_TILE_HALF);
        for (int e = tid; e < 2304; e += THREADS) cp16(sb + SM_A + e * 16, srcA + e * 16);
        asm volatile("cp.async.commit_group;");
        for (int e = tid; e < 1152; e += THREADS) cp16(sb + SM_B2 + e * 16, g_b2t + e * 16);
        asm volatile("cp.async.commit_group;");
        for (int e = tid; e < 1152; e += THREADS) cp16(sb + SM_B + e * 16, g_W2t + e * 16);
        asm volatile("cp.async.commit_group;");
        for (int e = tid; e < 1152; e += THREADS)
            cp16(sb + SM_B + B_SLOT + e * 16, g_W2t + B_SLOT + e * 16);
        asm volatile("cp.async.commit_group;");
    }

    // ---- f: fp32 into f_s, split bf16 into F tiles ----
    float* f_s = (float*)(smem + SM_FS);
    for (int e = tid; e < TILE_M * IN_F; e += THREADS) {
        const int m = e >> 6, c = e & 63;
        const float v = features[(size_t)(n0 + m) * IN_F + c];
        f_s[m * 68 + c] = v;
        __nv_bfloat16 hi = __float2bfloat16(v);
        __nv_bfloat16 lo = __float2bfloat16(v - __bfloat162float(hi));
        *(__nv_bfloat16*)(smem + SM_F + m * APITCH + c * 2)               = hi;
        *(__nv_bfloat16*)(smem + SM_F + A_TILE_HALF + m * APITCH + c * 2) = lo;
    }

    asm volatile("cp.async.wait_group 2;");  // A + b2 landed (B0/B1 may be in flight)
    __syncthreads();

    // ---- lane addressing constants (ldmatrix non-trans layouts) ----
    const int m0 = warp * 16;
    const uint32_t a_row  = ((lane >> 3) & 1) * 8 + (lane & 7);
    const uint32_t a_kadd = (lane >> 4) * 16;
    const uint32_t b_row  = ((lane >> 4) & 1) * 8 + (lane & 7);
    const uint32_t b_kadd = ((lane >> 3) & 1) * 16;

    // ---- preload A fragments for h (hi & lo) ----
    uint32_t Ah[4][4], Al[4][4];
    {
        const uint32_t base = sb + SM_A + (m0 + a_row) * APITCH + a_kadd;
#pragma unroll
        for (int ks = 0; ks < 4; ks++) ldsm_x4(Ah[ks], base + ks * 32);
#pragma unroll
        for (int ks = 0; ks < 4; ks++) ldsm_x4(Al[ks], base + A_TILE_HALF + ks * 32);
    }

    float acc[8][4];
#pragma unroll
    for (int nt = 0; nt < 8; nt++)
#pragma unroll
        for (int j = 0; j < 4; j++) acc[nt][j] = 0.0f;

    const int r0 = lane >> 2;  // local row within warp band (second row = r0+8)

    // ---- i-loop over 64 W2 slots (double-buffered cp.async stream) ----
    for (int i = 0; i < 64; i++) {
        const int buf = i & 1;
        if (i == 63) asm volatile("cp.async.wait_group 0;");
        else         asm volatile("cp.async.wait_group 1;");
        __syncthreads();

        float D[8][4];
        consume_slot(D, Ah, Al, sb + SM_B + buf * B_SLOT, b_row, b_kadd);

        const float fv0 = f_s[(m0 + r0) * 68 + i];
        const float fv1 = f_s[(m0 + r0 + 8) * 68 + i];
#pragma unroll
        for (int nt = 0; nt < 8; nt++) {
            acc[nt][0] = fmaf(fv0, D[nt][0], acc[nt][0]);
            acc[nt][1] = fmaf(fv0, D[nt][1], acc[nt][1]);
            acc[nt][2] = fmaf(fv1, D[nt][2], acc[nt][2]);
            acc[nt][3] = fmaf(fv1, D[nt][3], acc[nt][3]);
        }

        __syncthreads();  // all warps done reading buf before refill
        if (i + 2 < 64) {
            const uint8_t* src = g_W2t + (size_t)(i + 2) * B_SLOT;
            for (int e = tid; e < 1152; e += THREADS)
                cp16(sb + SM_B + buf * B_SLOT + e * 16, src + e * 16);
            asm volatile("cp.async.commit_group;");
        }
    }

    // ---- slot 64: bias term  acc += (f @ b2)  (A frags <- f tiles) ----
    {
        const uint32_t base = sb + SM_F + (m0 + a_row) * APITCH + a_kadd;
#pragma unroll
        for (int ks = 0; ks < 4; ks++) ldsm_x4(Ah[ks], base + ks * 32);
#pragma unroll
        for (int ks = 0; ks < 4; ks++) ldsm_x4(Al[ks], base + A_TILE_HALF + ks * 32);

        float D[8][4];
        consume_slot(D, Ah, Al, sb + SM_B2, b_row, b_kadd);
#pragma unroll
        for (int nt = 0; nt < 8; nt++)
#pragma unroll
            for (int j = 0; j < 4; j++) acc[nt][j] += D[nt][j];
    }

    // ---- epilogue: * ang, store ----
    const int gr0 = n0 + m0 + r0;
    const int gc  = (lane & 3) * 2;
#pragma unroll
    for (int nt = 0; nt < 8; nt++) {
        const int c = nt * 8 + gc;
        const float2 a0 = *(const float2*)(g_ang + (size_t)gr0 * OUT_F + c);
        const float2 a1 = *(const float2*)(g_ang + (size_t)(gr0 + 8) * OUT_F + c);
        float2 o0, o1;
        o0.x = acc[nt][0] * a0.x;  o0.y = acc[nt][1] * a0.y;
        o1.x = acc[nt][2] * a1.x;  o1.y = acc[nt][3] * a1.y;
        *(float2*)(out + (size_t)gr0 * OUT_F + c)       = o0;
        *(float2*)(out + (size_t)(gr0 + 8) * OUT_F + c) = o1;
    }
}

// ---------------------------------------------------------------------------
// Launch
// ---------------------------------------------------------------------------
extern "C" void kernel_launch(void* const* d_in, const int* in_sizes, int n_in,
                              void* d_out, int out_size)
{
    const float* features = (const float*)d_in[0];
    const float* radial   = (const float*)d_in[1];
    const float* angular  = (const float*)d_in[2];
    const float* W1       = (const float*)d_in[3];
    const float* b1       = (const float*)d_in[4];
    const float* W2       = (const float*)d_in[5];
    const float* b2       = (const float*)d_in[6];
    const float* Wa       = (const float*)d_in[7];
    const float* ba       = (const float*)d_in[8];
    float* out = (float*)d_out;
    (void)in_sizes; (void)n_in; (void)out_size;

    cudaFuncSetAttribute(tp_main, cudaFuncAttributeMaxDynamicSharedMemorySize, SMEM_BYTES);

    tp_precompute<<<NTOK / 64, THREADS>>>(radial, angular, W1, b1, Wa, ba);
    tp_w2split<<<(64 * 4096) / THREADS, THREADS>>>(W2);
    tp_b2split<<<4096 / THREADS, THREADS>>>(b2);
    tp_main<<<NTILES, THREADS, SMEM_BYTES>>>(features, out);
}

// round 4
// speedup vs baseline: 3.4741x; 1.3284x over previous
#include <cuda_runtime.h>
#include <cuda_fp16.h>
#include <math.h>
#include <stdint.h>

#define NTOK  65536
#define IN_F  64
#define OUT_F 64
#define RAD_F 32
#define ANG_F 16
#define HID   64

#define TILE_M   128
#define NTILES   (NTOK / TILE_M)   // 512
#define THREADS  256

#define APITCH      144            // padded row: 64 fp16 = 128B + 16B pad
#define A_TILE_HALF 18432          // 128 rows * 144 B
#define B_SLOT      9216           // 64 rows * 144 B (hi only)
#define STAGE       (2 * B_SLOT)   // 2 i-slots per pipeline stage

// ---------------------------------------------------------------------------
// Device-global scratch
// ---------------------------------------------------------------------------
__device__ __align__(1024) uint8_t g_A[(size_t)NTILES * 2 * A_TILE_HALF]; // h hi|lo
__device__ __align__(1024) uint8_t g_W2t[(size_t)64 * B_SLOT];            // B_i[o][k] fp16
__device__ __align__(1024) uint8_t g_b2t[B_SLOT];                         // b2 [o][i] fp16
__device__ float g_ang[(size_t)NTOK * OUT_F];

// ---------------------------------------------------------------------------
// Precompute 1: h = silu(radial@W1+b1) -> exact fp16 split (hi+lo); ang fp32.
// ---------------------------------------------------------------------------
__global__ void tp_precompute(const float* __restrict__ radial,
                              const float* __restrict__ angular,
                              const float* __restrict__ W1,
                              const float* __restrict__ b1,
                              const float* __restrict__ Wa,
                              const float* __restrict__ ba)
{
    __shared__ float sW1[RAD_F * HID];
    __shared__ float sWa[ANG_F * OUT_F];
    __shared__ float sb1[HID];
    __shared__ float sba[OUT_F];
    __shared__ float srad[64][RAD_F + 1];
    __shared__ float sang[64][ANG_F + 1];

    const int tid = threadIdx.x;
    const int n0  = blockIdx.x * 64;

    for (int idx = tid; idx < RAD_F * HID; idx += THREADS) sW1[idx] = W1[idx];
    for (int idx = tid; idx < ANG_F * OUT_F; idx += THREADS) sWa[idx] = Wa[idx];
    if (tid < HID)   sb1[tid] = b1[tid];
    if (tid < OUT_F) sba[tid] = ba[tid];
    for (int idx = tid; idx < 64 * RAD_F; idx += THREADS) {
        int t = idx >> 5, r = idx & 31;
        srad[t][r] = radial[(size_t)(n0 + t) * RAD_F + r];
    }
    for (int idx = tid; idx < 64 * ANG_F; idx += THREADS) {
        int t = idx >> 4, r = idx & 15;
        sang[t][r] = angular[(size_t)(n0 + t) * ANG_F + r];
    }
    __syncthreads();

    const int j = tid & 63;
    for (int tt = tid >> 6; tt < 64; tt += 4) {
        const int n = n0 + tt;

        float acch = sb1[j];
#pragma unroll
        for (int r = 0; r < RAD_F; r++) acch = fmaf(srad[tt][r], sW1[r * HID + j], acch);
        float hval = acch / (1.0f + expf(-acch));

        __half hi = __float2half_rn(hval);
        __half lo = __float2half_rn(hval - __half2float(hi));

        const int m    = n & (TILE_M - 1);
        const int tile = n >> 7;
        uint8_t* base = g_A + (size_t)tile * (2 * A_TILE_HALF) + m * APITCH + j * 2;
        *(__half*)base                 = hi;
        *(__half*)(base + A_TILE_HALF) = lo;

        float acca = sba[j];
#pragma unroll
        for (int r = 0; r < ANG_F; r++) acca = fmaf(sang[tt][r], sWa[r * OUT_F + j], acca);
        g_ang[(size_t)n * OUT_F + j] = acca;
    }
}

// ---------------------------------------------------------------------------
// Precompute 2: W2[k, i*64+o] -> B_i[o][k] fp16 (hi only); plus b2 tile.
// ---------------------------------------------------------------------------
__global__ void tp_wsplit(const float* __restrict__ W2, const float* __restrict__ b2)
{
    const int idx = blockIdx.x * THREADS + threadIdx.x;
    if (idx < 64 * 4096) {
        const int k  = idx >> 12;
        const int io = idx & 4095;
        const int o  = io & 63;
        const int i  = io >> 6;
        *(__half*)(g_W2t + (size_t)i * B_SLOT + o * APITCH + k * 2) =
            __float2half_rn(W2[idx]);
    } else if (idx < 64 * 4096 + 4096) {
        const int e = idx - 64 * 4096;
        const int i = e >> 6;
        const int o = e & 63;
        *(__half*)(g_b2t + o * APITCH + i * 2) = __float2half_rn(b2[e]);
    }
}

// ---------------------------------------------------------------------------
// PTX helpers (baseline sm_80+)
// ---------------------------------------------------------------------------
__device__ __forceinline__ void cp16(uint32_t s, const void* g) {
    asm volatile("cp.async.cg.shared.global [%0], [%1], 16;" :: "r"(s), "l"(g));
}
__device__ __forceinline__ void ldsm_x4(uint32_t* r, uint32_t addr) {
    asm volatile("ldmatrix.sync.aligned.m8n8.x4.shared.b16 {%0,%1,%2,%3}, [%4];"
        : "=r"(r[0]), "=r"(r[1]), "=r"(r[2]), "=r"(r[3]) : "r"(addr));
}
__device__ __forceinline__ void mma_f16(float* d, const uint32_t* a,
                                        uint32_t b0, uint32_t b1) {
    asm volatile(
        "mma.sync.aligned.m16n8k16.row.col.f32.f16.f16.f32 "
        "{%0,%1,%2,%3}, {%4,%5,%6,%7}, {%8,%9}, {%0,%1,%2,%3};"
        : "+f"(d[0]), "+f"(d[1]), "+f"(d[2]), "+f"(d[3])
        : "r"(a[0]), "r"(a[1]), "r"(a[2]), "r"(a[3]), "r"(b0), "r"(b1));
}

// ---------------------------------------------------------------------------
// SMEM layout (bytes)
// ---------------------------------------------------------------------------
#define SM_A    0u        // h tiles: hi | lo   (36864)
#define SM_F    36864u    // f tiles: hi | lo   (36864)
#define SM_B    73728u    // 4 stages x 18432   (73728)
#define SM_B2   147456u   // b2 tile            (9216)
#define SM_FS   156672u   // f fp32 [128][68]   (34816)
#define SMEM_BYTES 191488

// 2-pass split consume: D = Ah*Bh + Al*Bh  (fp32 accum)
__device__ __forceinline__ void consume2(float D[8][4],
                                         const uint32_t Ah[4][4],
                                         const uint32_t Al[4][4],
                                         uint32_t bbase,
                                         uint32_t b_row, uint32_t b_kadd)
{
#pragma unroll
    for (int nt = 0; nt < 8; nt++)
#pragma unroll
        for (int j = 0; j < 4; j++) D[nt][j] = 0.0f;

#pragma unroll
    for (int ks = 0; ks < 4; ks++) {
        uint32_t bh[16];
#pragma unroll
        for (int g = 0; g < 4; g++)
            ldsm_x4(bh + 4 * g,
                    bbase + (g * 16 + b_row) * APITCH + ks * 32 + b_kadd);
#pragma unroll
        for (int nt = 0; nt < 8; nt++) {
            const uint32_t b0 = bh[(nt >> 1) * 4 + (nt & 1) * 2];
            const uint32_t b1 = bh[(nt >> 1) * 4 + (nt & 1) * 2 + 1];
            mma_f16(D[nt], Ah[ks], b0, b1);
            mma_f16(D[nt], Al[ks], b0, b1);
        }
    }
}

// ---------------------------------------------------------------------------
// Main kernel
// ---------------------------------------------------------------------------
__global__ __launch_bounds__(THREADS, 1)
void tp_main(const float* __restrict__ features, float* __restrict__ out)
{
    extern __shared__ __align__(1024) uint8_t smem[];
    const uint32_t sb = (uint32_t)__cvta_generic_to_shared(smem);
    const int tid  = threadIdx.x;
    const int lane = tid & 31;
    const int warp = tid >> 5;
    const int tile = blockIdx.x;
    const int n0   = tile * TILE_M;

    // ---- group 0: A tile + b2 tile ----
    {
        const uint8_t* srcA = g_A + (size_t)tile * (2 * A_TILE_HALF);
        for (int e = tid; e < 2304; e += THREADS) cp16(sb + SM_A + e * 16, srcA + e * 16);
        for (int e = tid; e < 576; e += THREADS)  cp16(sb + SM_B2 + e * 16, g_b2t + e * 16);
        asm volatile("cp.async.commit_group;");
    }
    // ---- groups 1..3: pipeline stages 0..2 (slots 0..5) ----
#pragma unroll
    for (int s = 0; s < 3; s++) {
        const uint8_t* src = g_W2t + (size_t)s * STAGE;
        for (int e = tid; e < 1152; e += THREADS)
            cp16(sb + SM_B + s * STAGE + e * 16, src + e * 16);
        asm volatile("cp.async.commit_group;");
    }

    // ---- f: fp32 into f_s, exact fp16 split into F tiles ----
    float* f_s = (float*)(smem + SM_FS);
    for (int e = tid; e < TILE_M * IN_F; e += THREADS) {
        const int m = e >> 6, c = e & 63;
        const float v = features[(size_t)(n0 + m) * IN_F + c];
        f_s[m * 68 + c] = v;
        __half hi = __float2half_rn(v);
        __half lo = __float2half_rn(v - __half2float(hi));
        *(__half*)(smem + SM_F + m * APITCH + c * 2)               = hi;
        *(__half*)(smem + SM_F + A_TILE_HALF + m * APITCH + c * 2) = lo;
    }

    asm volatile("cp.async.wait_group 3;");   // group 0 (A, b2) landed
    __syncthreads();

    // ---- lane addressing (ldmatrix non-trans; layout validated in R3) ----
    const int m0 = warp * 16;
    const uint32_t a_row  = ((lane >> 3) & 1) * 8 + (lane & 7);
    const uint32_t a_kadd = (lane >> 4) * 16;
    const uint32_t b_row  = ((lane >> 4) & 1) * 8 + (lane & 7);
    const uint32_t b_kadd = ((lane >> 3) & 1) * 16;

    // ---- preload A fragments (h hi & lo) ----
    uint32_t Ah[4][4], Al[4][4];
    {
        const uint32_t base = sb + SM_A + (m0 + a_row) * APITCH + a_kadd;
#pragma unroll
        for (int ks = 0; ks < 4; ks++) ldsm_x4(Ah[ks], base + ks * 32);
#pragma unroll
        for (int ks = 0; ks < 4; ks++) ldsm_x4(Al[ks], base + A_TILE_HALF + ks * 32);
    }

    float acc[8][4];
#pragma unroll
    for (int nt = 0; nt < 8; nt++)
#pragma unroll
        for (int j = 0; j < 4; j++) acc[nt][j] = 0.0f;

    const int r0 = lane >> 2;

    // ---- 32 iterations, 2 i-slots each; 4-stage pipeline, 1 sync/iter ----
    for (int j = 0; j < 32; j++) {
        if (j < 30)       asm volatile("cp.async.wait_group 2;");
        else if (j == 30) asm volatile("cp.async.wait_group 1;");
        else              asm volatile("cp.async.wait_group 0;");
        __syncthreads();

        const uint32_t bbase = sb + SM_B + (j & 3) * STAGE;

#pragma unroll
        for (int half = 0; half < 2; half++) {
            const int i = 2 * j + half;
            float D[8][4];
            consume2(D, Ah, Al, bbase + half * B_SLOT, b_row, b_kadd);

            const float fv0 = f_s[(m0 + r0) * 68 + i];
            const float fv1 = f_s[(m0 + r0 + 8) * 68 + i];
#pragma unroll
            for (int nt = 0; nt < 8; nt++) {
                acc[nt][0] = fmaf(fv0, D[nt][0], acc[nt][0]);
                acc[nt][1] = fmaf(fv0, D[nt][1], acc[nt][1]);
                acc[nt][2] = fmaf(fv1, D[nt][2], acc[nt][2]);
                acc[nt][3] = fmaf(fv1, D[nt][3], acc[nt][3]);
            }
        }

        // refill buffer consumed at iter j-1 (safe: everyone passed this
        // iter's syncthreads, hence finished iter j-1)
        if (j + 3 < 32) {
            const uint8_t* src = g_W2t + (size_t)(j + 3) * STAGE;
            const uint32_t dst = sb + SM_B + ((j + 3) & 3) * STAGE;
            for (int e = tid; e < 1152; e += THREADS)
                cp16(dst + e * 16, src + e * 16);
            asm volatile("cp.async.commit_group;");
        }
    }

    // ---- bias slot: acc += f @ b2  (A frags <- split f tiles) ----
    {
        const uint32_t base = sb + SM_F + (m0 + a_row) * APITCH + a_kadd;
#pragma unroll
        for (int ks = 0; ks < 4; ks++) ldsm_x4(Ah[ks], base + ks * 32);
#pragma unroll
        for (int ks = 0; ks < 4; ks++) ldsm_x4(Al[ks], base + A_TILE_HALF + ks * 32);

        float D[8][4];
        consume2(D, Ah, Al, sb + SM_B2, b_row, b_kadd);
#pragma unroll
        for (int nt = 0; nt < 8; nt++)
#pragma unroll
            for (int j = 0; j < 4; j++) acc[nt][j] += D[nt][j];
    }

    // ---- epilogue: * ang, store ----
    const int gr0 = n0 + m0 + r0;
    const int gc  = (lane & 3) * 2;
#pragma unroll
    for (int nt = 0; nt < 8; nt++) {
        const int c = nt * 8 + gc;
        const float2 a0 = *(const float2*)(g_ang + (size_t)gr0 * OUT_F + c);
        const float2 a1 = *(const float2*)(g_ang + (size_t)(gr0 + 8) * OUT_F + c);
        float2 o0, o1;
        o0.x = acc[nt][0] * a0.x;  o0.y = acc[nt][1] * a0.y;
        o1.x = acc[nt][2] * a1.x;  o1.y = acc[nt][3] * a1.y;
        *(float2*)(out + (size_t)gr0 * OUT_F + c)       = o0;
        *(float2*)(out + (size_t)(gr0 + 8) * OUT_F + c) = o1;
    }
}

// ---------------------------------------------------------------------------
// Launch
// ---------------------------------------------------------------------------
extern "C" void kernel_launch(void* const* d_in, const int* in_sizes, int n_in,
                              void* d_out, int out_size)
{
    const float* features = (const float*)d_in[0];
    const float* radial   = (const float*)d_in[1];
    const float* angular  = (const float*)d_in[2];
    const float* W1       = (const float*)d_in[3];
    const float* b1       = (const float*)d_in[4];
    const float* W2       = (const float*)d_in[5];
    const float* b2       = (const float*)d_in[6];
    const float* Wa       = (const float*)d_in[7];
    const float* ba       = (const float*)d_in[8];
    float* out = (float*)d_out;
    (void)in_sizes; (void)n_in; (void)out_size;

    cudaFuncSetAttribute(tp_main, cudaFuncAttributeMaxDynamicSharedMemorySize, SMEM_BYTES);

    tp_precompute<<<NTOK / 64, THREADS>>>(radial, angular, W1, b1, Wa, ba);
    tp_wsplit<<<(64 * 4096 + 4096 + THREADS - 1) / THREADS, THREADS>>>(W2, b2);
    tp_main<<<NTILES, THREADS, SMEM_BYTES>>>(features, out);
}

// round 5
// speedup vs baseline: 4.6207x; 1.3300x over previous
#include <cuda_runtime.h>
#include <cuda_fp16.h>
#include <math.h>
#include <stdint.h>

#define NTOK  65536
#define IN_F  64
#define OUT_F 64
#define RAD_F 32
#define ANG_F 16
#define HID   64

#define TILE_M   128
#define NTILES   (NTOK / TILE_M)   // 512
#define THREADS  256

#define APITCH   144               // padded row: 64 fp16 = 128B + 16B pad
#define A_TILE   18432             // 128 rows * 144 B
#define B_SLOT   9216              // 64 rows * 144 B
#define STAGE    (2 * B_SLOT)      // 2 i-slots per pipeline stage

// ---------------------------------------------------------------------------
// Device-global scratch (weights only; ~600 KB)
// ---------------------------------------------------------------------------
__device__ __align__(1024) uint8_t g_W2t[(size_t)64 * B_SLOT];  // B_i[o][k] fp16
__device__ __align__(1024) uint8_t g_b2t[B_SLOT];               // b2 [o][i] fp16

// ---------------------------------------------------------------------------
// Precompute: W2[k, i*64+o] -> B_i[o][k] fp16; b2 -> tile [o][i] fp16.
// ---------------------------------------------------------------------------
__global__ void tp_wsplit(const float* __restrict__ W2, const float* __restrict__ b2)
{
    const int idx = blockIdx.x * THREADS + threadIdx.x;
    if (idx < 64 * 4096) {
        const int k  = idx >> 12;
        const int io = idx & 4095;
        const int o  = io & 63;
        const int i  = io >> 6;
        *(__half*)(g_W2t + (size_t)i * B_SLOT + o * APITCH + k * 2) =
            __float2half_rn(W2[idx]);
    } else if (idx < 64 * 4096 + 4096) {
        const int e = idx - 64 * 4096;
        const int i = e >> 6;
        const int o = e & 63;
        *(__half*)(g_b2t + o * APITCH + i * 2) = __float2half_rn(b2[e]);
    }
}

// ---------------------------------------------------------------------------
// PTX helpers (baseline sm_80+)
// ---------------------------------------------------------------------------
__device__ __forceinline__ void cp16(uint32_t s, const void* g) {
    asm volatile("cp.async.cg.shared.global [%0], [%1], 16;" :: "r"(s), "l"(g));
}
__device__ __forceinline__ void ldsm_x4(uint32_t* r, uint32_t addr) {
    asm volatile("ldmatrix.sync.aligned.m8n8.x4.shared.b16 {%0,%1,%2,%3}, [%4];"
        : "=r"(r[0]), "=r"(r[1]), "=r"(r[2]), "=r"(r[3]) : "r"(addr));
}
__device__ __forceinline__ void mma_f16(float* d, const uint32_t* a,
                                        uint32_t b0, uint32_t b1) {
    asm volatile(
        "mma.sync.aligned.m16n8k16.row.col.f32.f16.f16.f32 "
        "{%0,%1,%2,%3}, {%4,%5,%6,%7}, {%8,%9}, {%0,%1,%2,%3};"
        : "+f"(d[0]), "+f"(d[1]), "+f"(d[2]), "+f"(d[3])
        : "r"(a[0]), "r"(a[1]), "r"(a[2]), "r"(a[3]), "r"(b0), "r"(b1));
}

// ---------------------------------------------------------------------------
// SMEM layout (bytes)
// ---------------------------------------------------------------------------
#define SM_A    0u        // h fp16 tile            (18432)
#define SM_F    18432u    // f fp16 tile            (18432)
#define SM_B    36864u    // 4 stages x 18432       (73728)
#define SM_B2   110592u   // b2 tile                (9216)
#define SM_FS   119808u   // f fp32 [128][68]       (34816)
#define SM_RAD  154624u   // radial fp32 [128][32]  (16384)
#define SM_ANG  171008u   // angular fp32 [128][17] (8704)
#define SM_W1   179712u   // W1 fp32 [32][64]       (8192)
#define SM_WA   187904u   // Wa fp32 [16][64]       (4096)
#define SM_B1   192000u   // b1 fp32 [64]           (256)
#define SM_BA   192256u   // ba fp32 [64]           (256)
#define SMEM_BYTES 192512

// 1-pass consume: D = A * B  (fp32 accum)
__device__ __forceinline__ void consume1(float D[8][4],
                                         const uint32_t Ah[4][4],
                                         uint32_t bbase,
                                         uint32_t b_row, uint32_t b_kadd)
{
#pragma unroll
    for (int nt = 0; nt < 8; nt++)
#pragma unroll
        for (int j = 0; j < 4; j++) D[nt][j] = 0.0f;

#pragma unroll
    for (int ks = 0; ks < 4; ks++) {
        uint32_t bh[16];
#pragma unroll
        for (int g = 0; g < 4; g++)
            ldsm_x4(bh + 4 * g,
                    bbase + (g * 16 + b_row) * APITCH + ks * 32 + b_kadd);
#pragma unroll
        for (int nt = 0; nt < 8; nt++) {
            const uint32_t b0 = bh[(nt >> 1) * 4 + (nt & 1) * 2];
            const uint32_t b1 = bh[(nt >> 1) * 4 + (nt & 1) * 2 + 1];
            mma_f16(D[nt], Ah[ks], b0, b1);
        }
    }
}

// ---------------------------------------------------------------------------
// Fused main kernel
// ---------------------------------------------------------------------------
__global__ __launch_bounds__(THREADS, 1)
void tp_main(const float* __restrict__ features,
             const float* __restrict__ radial,
             const float* __restrict__ angular,
             const float* __restrict__ W1,
             const float* __restrict__ b1,
             const float* __restrict__ Wa,
             const float* __restrict__ ba,
             float* __restrict__ out)
{
    extern __shared__ __align__(1024) uint8_t smem[];
    const uint32_t sb = (uint32_t)__cvta_generic_to_shared(smem);
    const int tid  = threadIdx.x;
    const int lane = tid & 31;
    const int warp = tid >> 5;
    const int tile = blockIdx.x;
    const int n0   = tile * TILE_M;

    // ---- cp.async: groups g0..g2 = B stages 0..2, g3 = b2 tile ----
#pragma unroll
    for (int s = 0; s < 3; s++) {
        const uint8_t* src = g_W2t + (size_t)s * STAGE;
        for (int e = tid; e < 1152; e += THREADS)
            cp16(sb + SM_B + s * STAGE + e * 16, src + e * 16);
        asm volatile("cp.async.commit_group;");
    }
    for (int e = tid; e < 576; e += THREADS) cp16(sb + SM_B2 + e * 16, g_b2t + e * 16);
    asm volatile("cp.async.commit_group;");

    // ---- stage small operands + f (overlaps with cp.async) ----
    float* f_s   = (float*)(smem + SM_FS);
    float* srad  = (float*)(smem + SM_RAD);   // [128][32]
    float* sang  = (float*)(smem + SM_ANG);   // [128][17]
    float* sW1   = (float*)(smem + SM_W1);    // [32][64]
    float* sWa   = (float*)(smem + SM_WA);    // [16][64]
    float* sb1_  = (float*)(smem + SM_B1);
    float* sba_  = (float*)(smem + SM_BA);

    for (int e = tid; e < TILE_M * IN_F; e += THREADS) {
        const int m = e >> 6, c = e & 63;
        const float v = features[(size_t)(n0 + m) * IN_F + c];
        f_s[m * 68 + c] = v;
        *(__half*)(smem + SM_F + m * APITCH + c * 2) = __float2half_rn(v);
    }
    for (int e = tid; e < TILE_M * RAD_F; e += THREADS) {
        const int m = e >> 5, r = e & 31;
        srad[m * 32 + r] = radial[(size_t)(n0 + m) * RAD_F + r];
    }
    for (int e = tid; e < TILE_M * ANG_F; e += THREADS) {
        const int m = e >> 4, r = e & 15;
        sang[m * 17 + r] = angular[(size_t)(n0 + m) * ANG_F + r];
    }
    for (int e = tid; e < RAD_F * HID; e += THREADS) sW1[e] = W1[e];
    for (int e = tid; e < ANG_F * OUT_F; e += THREADS) sWa[e] = Wa[e];
    if (tid < HID)   sb1_[tid] = b1[tid];
    else if (tid < HID + OUT_F) sba_[tid - HID] = ba[tid - HID];
    __syncthreads();

    // ---- compute h = silu(radial@W1+b1) -> A tile (fp16, padded) ----
    {
        const int j = tid & 63;
        const int mb = tid >> 6;
#pragma unroll 4
        for (int s = 0; s < 32; s++) {
            const int m = mb + s * 4;
            float a = sb1_[j];
#pragma unroll
            for (int r = 0; r < RAD_F; r++)
                a = fmaf(srad[m * 32 + r], sW1[r * HID + j], a);
            const float hv = a / (1.0f + expf(-a));
            *(__half*)(smem + SM_A + m * APITCH + j * 2) = __float2half_rn(hv);
        }
    }
    __syncthreads();

    // ---- lane addressing (ldmatrix non-trans; validated R3/R4) ----
    const int m0 = warp * 16;
    const uint32_t a_row  = ((lane >> 3) & 1) * 8 + (lane & 7);
    const uint32_t a_kadd = (lane >> 4) * 16;
    const uint32_t b_row  = ((lane >> 4) & 1) * 8 + (lane & 7);
    const uint32_t b_kadd = ((lane >> 3) & 1) * 16;

    uint32_t Ah[4][4];
    {
        const uint32_t base = sb + SM_A + (m0 + a_row) * APITCH + a_kadd;
#pragma unroll
        for (int ks = 0; ks < 4; ks++) ldsm_x4(Ah[ks], base + ks * 32);
    }

    float acc[8][4];
#pragma unroll
    for (int nt = 0; nt < 8; nt++)
#pragma unroll
        for (int j = 0; j < 4; j++) acc[nt][j] = 0.0f;

    const int r0 = lane >> 2;

    // ---- 32 iterations x 2 i-slots; 4-stage pipeline, 1 sync/iter ----
    for (int j = 0; j < 32; j++) {
        if (j < 30)       asm volatile("cp.async.wait_group 2;");
        else if (j == 30) asm volatile("cp.async.wait_group 1;");
        else              asm volatile("cp.async.wait_group 0;");
        __syncthreads();

        const uint32_t bbase = sb + SM_B + (j & 3) * STAGE;

#pragma unroll
        for (int half = 0; half < 2; half++) {
            const int i = 2 * j + half;
            float D[8][4];
            consume1(D, Ah, bbase + half * B_SLOT, b_row, b_kadd);

            const float fv0 = f_s[(m0 + r0) * 68 + i];
            const float fv1 = f_s[(m0 + r0 + 8) * 68 + i];
#pragma unroll
            for (int nt = 0; nt < 8; nt++) {
                acc[nt][0] = fmaf(fv0, D[nt][0], acc[nt][0]);
                acc[nt][1] = fmaf(fv0, D[nt][1], acc[nt][1]);
                acc[nt][2] = fmaf(fv1, D[nt][2], acc[nt][2]);
                acc[nt][3] = fmaf(fv1, D[nt][3], acc[nt][3]);
            }
        }

        if (j + 3 < 32) {
            const uint8_t* src = g_W2t + (size_t)(j + 3) * STAGE;
            const uint32_t dst = sb + SM_B + ((j + 3) & 3) * STAGE;
            for (int e = tid; e < 1152; e += THREADS)
                cp16(dst + e * 16, src + e * 16);
            asm volatile("cp.async.commit_group;");
        }
    }

    // ---- bias slot: acc += f @ b2 (A frags <- f fp16 tile) ----
    {
        uint32_t Fh[4][4];
        const uint32_t base = sb + SM_F + (m0 + a_row) * APITCH + a_kadd;
#pragma unroll
        for (int ks = 0; ks < 4; ks++) ldsm_x4(Fh[ks], base + ks * 32);

        float D[8][4];
        consume1(D, Fh, sb + SM_B2, b_row, b_kadd);
#pragma unroll
        for (int nt = 0; nt < 8; nt++)
#pragma unroll
            for (int j = 0; j < 4; j++) acc[nt][j] += D[nt][j];
    }

    // ---- epilogue: compute ang = angular@Wa+ba on the fly, multiply, store ----
    float sa0[16], sa1[16];
#pragma unroll
    for (int q = 0; q < 16; q++) {
        sa0[q] = sang[(m0 + r0) * 17 + q];
        sa1[q] = sang[(m0 + r0 + 8) * 17 + q];
    }

    const int gr0 = n0 + m0 + r0;
    const int gc  = (lane & 3) * 2;
#pragma unroll
    for (int nt = 0; nt < 8; nt++) {
        const int c0 = nt * 8 + gc;
        float a00 = sba_[c0], a01 = sba_[c0 + 1];
        float a10 = a00,      a11 = a01;
#pragma unroll
        for (int q = 0; q < 16; q++) {
            const float w0 = sWa[q * 64 + c0];
            const float w1 = sWa[q * 64 + c0 + 1];
            a00 = fmaf(sa0[q], w0, a00);  a01 = fmaf(sa0[q], w1, a01);
            a10 = fmaf(sa1[q], w0, a10);  a11 = fmaf(sa1[q], w1, a11);
        }
        float2 o0, o1;
        o0.x = acc[nt][0] * a00;  o0.y = acc[nt][1] * a01;
        o1.x = acc[nt][2] * a10;  o1.y = acc[nt][3] * a11;
        *(float2*)(out + (size_t)gr0 * OUT_F + c0)       = o0;
        *(float2*)(out + (size_t)(gr0 + 8) * OUT_F + c0) = o1;
    }
}

// ---------------------------------------------------------------------------
// Launch
// ---------------------------------------------------------------------------
extern "C" void kernel_launch(void* const* d_in, const int* in_sizes, int n_in,
                              void* d_out, int out_size)
{
    const float* features = (const float*)d_in[0];
    const float* radial   = (const float*)d_in[1];
    const float* angular  = (const float*)d_in[2];
    const float* W1       = (const float*)d_in[3];
    const float* b1       = (const float*)d_in[4];
    const float* W2       = (const float*)d_in[5];
    const float* b2       = (const float*)d_in[6];
    const float* Wa       = (const float*)d_in[7];
    const float* ba       = (const float*)d_in[8];
    float* out = (float*)d_out;
    (void)in_sizes; (void)n_in; (void)out_size;

    cudaFuncSetAttribute(tp_main, cudaFuncAttributeMaxDynamicSharedMemorySize, SMEM_BYTES);

    tp_wsplit<<<(64 * 4096 + 4096 + THREADS - 1) / THREADS, THREADS>>>(W2, b2);
    tp_main<<<NTILES, THREADS, SMEM_BYTES>>>(features, radial, angular,
                                             W1, b1, Wa, ba, out);
}

// round 7
// speedup vs baseline: 5.7231x; 1.2386x over previous
#include <cuda_runtime.h>
#include <cuda_fp16.h>
#include <math.h>
#include <stdint.h>

#define NTOK  65536
#define IN_F  64
#define OUT_F 64
#define RAD_F 32
#define ANG_F 16
#define HID   64

#define TILE_M   256
#define NTILES   (NTOK / TILE_M)   // 256
#define THREADS  256

#define APITCH   144               // padded row: 64 fp16 = 128B + 16B pad
#define B_SLOT   9216              // 64 rows * 144 B
#define STAGE    (2 * B_SLOT)      // 2 i-slots per pipeline stage

// ---------------------------------------------------------------------------
// Device-global scratch (weights only)
// ---------------------------------------------------------------------------
__device__ __align__(1024) uint8_t g_W2t[(size_t)64 * B_SLOT];  // B_i[o][k] fp16
__device__ __align__(1024) uint8_t g_b2t[B_SLOT];               // b2 [o][i] fp16

__global__ void tp_wsplit(const float* __restrict__ W2, const float* __restrict__ b2)
{
    const int idx = blockIdx.x * THREADS + threadIdx.x;
    if (idx < 64 * 4096) {
        const int k  = idx >> 12;
        const int io = idx & 4095;
        const int o  = io & 63;
        const int i  = io >> 6;
        *(__half*)(g_W2t + (size_t)i * B_SLOT + o * APITCH + k * 2) =
            __float2half_rn(W2[idx]);
    } else if (idx < 64 * 4096 + 4096) {
        const int e = idx - 64 * 4096;
        const int i = e >> 6;
        const int o = e & 63;
        *(__half*)(g_b2t + o * APITCH + i * 2) = __float2half_rn(b2[e]);
    }
}

// ---------------------------------------------------------------------------
// PTX helpers (baseline sm_80+)
// ---------------------------------------------------------------------------
__device__ __forceinline__ void cp16(uint32_t s, const void* g) {
    asm volatile("cp.async.cg.shared.global [%0], [%1], 16;" :: "r"(s), "l"(g));
}
__device__ __forceinline__ void ldsm_x4(uint32_t* r, uint32_t addr) {
    asm volatile("ldmatrix.sync.aligned.m8n8.x4.shared.b16 {%0,%1,%2,%3}, [%4];"
        : "=r"(r[0]), "=r"(r[1]), "=r"(r[2]), "=r"(r[3]) : "r"(addr));
}
__device__ __forceinline__ void mma_f16(float* d, const uint32_t* a,
                                        uint32_t b0, uint32_t b1) {
    asm volatile(
        "mma.sync.aligned.m16n8k16.row.col.f32.f16.f16.f32 "
        "{%0,%1,%2,%3}, {%4,%5,%6,%7}, {%8,%9}, {%0,%1,%2,%3};"
        : "+f"(d[0]), "+f"(d[1]), "+f"(d[2]), "+f"(d[3])
        : "r"(a[0]), "r"(a[1]), "r"(a[2]), "r"(a[3]), "r"(b0), "r"(b1));
}
__device__ __forceinline__ uint32_t hmul2u(uint32_t a, uint32_t f) {
    uint32_t d;
    asm("mul.rn.f16x2 %0, %1, %2;" : "=r"(d) : "r"(a), "r"(f));
    return d;
}
__device__ __forceinline__ uint32_t hdup(uint32_t smem_addr) {
    uint32_t h;
    asm volatile("ld.shared.u16 %0, [%1];" : "=r"(h) : "r"(smem_addr));
    return h | (h << 16);
}

// ---------------------------------------------------------------------------
// SMEM layout (bytes)
// ---------------------------------------------------------------------------
#define SM_A    0u        // h fp16 tile 256 rows     (36864)
#define SM_F    36864u    // f fp16 tile 256 rows     (36864)
#define SM_B    73728u    // 4 stages x 18432         (73728)
#define SM_B2   147456u   // b2 tile                  (9216)
#define SM_RAD  156672u   // radial fp32 [256][32]    (32768)
#define SM_ANG  189440u   // angular fp32 [256][17]   (17408)
#define SM_W1   206848u   // W1 fp32 [32][64]         (8192)
#define SM_WA   215040u   // Wa fp32 [16][64]         (4096)
#define SM_B1   219136u   // b1 fp32 [64]             (256)
#define SM_BA   219392u   // ba fp32 [64]             (256)
#define SMEM_BYTES 219648

// ---------------------------------------------------------------------------
// Fused main kernel: 256 tokens/CTA, 8 warps, 32 rows/warp (2 m16 bands)
// ---------------------------------------------------------------------------
__global__ __launch_bounds__(THREADS, 1)
void tp_main(const float* __restrict__ features,
             const float* __restrict__ radial,
             const float* __restrict__ angular,
             const float* __restrict__ W1,
             const float* __restrict__ b1,
             const float* __restrict__ Wa,
             const float* __restrict__ ba,
             float* __restrict__ out)
{
    extern __shared__ __align__(1024) uint8_t smem[];
    const uint32_t sb = (uint32_t)__cvta_generic_to_shared(smem);
    const int tid  = threadIdx.x;
    const int lane = tid & 31;
    const int warp = tid >> 5;
    const int n0   = blockIdx.x * TILE_M;

    // ---- cp.async groups: g0..g2 = B stages 0..2, g3 = b2 tile ----
#pragma unroll
    for (int s = 0; s < 3; s++) {
        const uint8_t* src = g_W2t + (size_t)s * STAGE;
        for (int e = tid; e < 1152; e += THREADS)
            cp16(sb + SM_B + s * STAGE + e * 16, src + e * 16);
        asm volatile("cp.async.commit_group;");
    }
    for (int e = tid; e < 576; e += THREADS) cp16(sb + SM_B2 + e * 16, g_b2t + e * 16);
    asm volatile("cp.async.commit_group;");

    // ---- stage inputs (overlaps cp.async) ----
    float* srad = (float*)(smem + SM_RAD);   // [256][32]
    float* sang = (float*)(smem + SM_ANG);   // [256][17]
    float* sW1  = (float*)(smem + SM_W1);
    float* sWa  = (float*)(smem + SM_WA);
    float* sb1_ = (float*)(smem + SM_B1);
    float* sba_ = (float*)(smem + SM_BA);

    for (int e = tid; e < TILE_M * IN_F; e += THREADS) {
        const int m = e >> 6, c = e & 63;
        const float v = features[(size_t)(n0 + m) * IN_F + c];
        *(__half*)(smem + SM_F + m * APITCH + c * 2) = __float2half_rn(v);
    }
    for (int e = tid; e < TILE_M * RAD_F; e += THREADS) {
        const int m = e >> 5, r = e & 31;
        srad[m * 32 + r] = radial[(size_t)(n0 + m) * RAD_F + r];
    }
    for (int e = tid; e < TILE_M * ANG_F; e += THREADS) {
        const int m = e >> 4, r = e & 15;
        sang[m * 17 + r] = angular[(size_t)(n0 + m) * ANG_F + r];
    }
    for (int e = tid; e < RAD_F * HID; e += THREADS) sW1[e] = W1[e];
    for (int e = tid; e < ANG_F * OUT_F; e += THREADS) sWa[e] = Wa[e];
    if (tid < HID)   sb1_[tid] = b1[tid];
    else if (tid < HID + OUT_F) sba_[tid - HID] = ba[tid - HID];
    __syncthreads();

    // ---- h = silu(radial@W1+b1) -> A tile (fp16) ----
    {
        const int j  = tid & 63;
        const int mb = tid >> 6;
#pragma unroll 4
        for (int s = 0; s < TILE_M / 4; s++) {
            const int m = mb + s * 4;
            float a = sb1_[j];
#pragma unroll
            for (int r = 0; r < RAD_F; r++)
                a = fmaf(srad[m * 32 + r], sW1[r * HID + j], a);
            const float hv = a / (1.0f + expf(-a));
            *(__half*)(smem + SM_A + m * APITCH + j * 2) = __float2half_rn(hv);
        }
    }
    __syncthreads();

    // ---- lane addressing (validated R3-R5) ----
    const int m0 = warp * 32;
    const uint32_t a_row  = ((lane >> 3) & 1) * 8 + (lane & 7);
    const uint32_t a_kadd = (lane >> 4) * 16;
    const uint32_t b_row  = ((lane >> 4) & 1) * 8 + (lane & 7);
    const uint32_t b_kadd = ((lane >> 3) & 1) * 16;
    const int r0 = lane >> 2;

    // ---- preload raw A fragments for both bands ----
    uint32_t Ah0[4][4], Ah1[4][4];
    {
        const uint32_t base0 = sb + SM_A + (m0 + a_row) * APITCH + a_kadd;
        const uint32_t base1 = base0 + 16 * APITCH;
#pragma unroll
        for (int ks = 0; ks < 4; ks++) ldsm_x4(Ah0[ks], base0 + ks * 32);
#pragma unroll
        for (int ks = 0; ks < 4; ks++) ldsm_x4(Ah1[ks], base1 + ks * 32);
    }

    float acc0[8][4], acc1[8][4];
#pragma unroll
    for (int nt = 0; nt < 8; nt++)
#pragma unroll
        for (int j = 0; j < 4; j++) { acc0[nt][j] = 0.0f; acc1[nt][j] = 0.0f; }

    // f fp16 smem addresses for the 4 rows this thread owns
    const uint32_t fa0 = sb + SM_F + (m0 + r0) * APITCH;       // band0 row r0
    const uint32_t fa1 = fa0 + 8 * APITCH;                     // band0 row r0+8
    const uint32_t fa2 = fa0 + 16 * APITCH;                    // band1 row r0
    const uint32_t fa3 = fa0 + 24 * APITCH;                    // band1 row r0+8

    // ---- 32 iterations x 2 i-slots; 4-stage pipeline, 1 sync/iter ----
    for (int j = 0; j < 32; j++) {
        if (j < 30)       asm volatile("cp.async.wait_group 2;");
        else if (j == 30) asm volatile("cp.async.wait_group 1;");
        else              asm volatile("cp.async.wait_group 0;");
        __syncthreads();

        const uint32_t bbase = sb + SM_B + (j & 3) * STAGE;

#pragma unroll
        for (int half = 0; half < 2; half++) {
            const int i = 2 * j + half;
            const uint32_t sbb = bbase + half * B_SLOT;

            const uint32_t f0 = hdup(fa0 + i * 2);
            const uint32_t f1 = hdup(fa1 + i * 2);
            const uint32_t f2 = hdup(fa2 + i * 2);
            const uint32_t f3 = hdup(fa3 + i * 2);

#pragma unroll
            for (int ks = 0; ks < 4; ks++) {
                uint32_t bh[16];
#pragma unroll
                for (int g = 0; g < 4; g++)
                    ldsm_x4(bh + 4 * g,
                            sbb + (g * 16 + b_row) * APITCH + ks * 32 + b_kadd);

                // A frag reg layout (m16n8k16): regs {0,2} = row r0,
                // regs {1,3} = row r0+8.  Scale accordingly.
                uint32_t As0[4], As1[4];
                As0[0] = hmul2u(Ah0[ks][0], f0);
                As0[1] = hmul2u(Ah0[ks][1], f1);
                As0[2] = hmul2u(Ah0[ks][2], f0);
                As0[3] = hmul2u(Ah0[ks][3], f1);
                As1[0] = hmul2u(Ah1[ks][0], f2);
                As1[1] = hmul2u(Ah1[ks][1], f3);
                As1[2] = hmul2u(Ah1[ks][2], f2);
                As1[3] = hmul2u(Ah1[ks][3], f3);

#pragma unroll
                for (int nt = 0; nt < 8; nt++) {
                    const uint32_t b0 = bh[(nt >> 1) * 4 + (nt & 1) * 2];
                    const uint32_t b1v = bh[(nt >> 1) * 4 + (nt & 1) * 2 + 1];
                    mma_f16(acc0[nt], As0, b0, b1v);
                    mma_f16(acc1[nt], As1, b0, b1v);
                }
            }
        }

        if (j + 3 < 32) {
            const uint8_t* src = g_W2t + (size_t)(j + 3) * STAGE;
            const uint32_t dst = sb + SM_B + ((j + 3) & 3) * STAGE;
            for (int e = tid; e < 1152; e += THREADS)
                cp16(dst + e * 16, src + e * 16);
            asm volatile("cp.async.commit_group;");
        }
    }

    // ---- bias slot: acc += f @ b2 (unscaled F fragments) ----
    {
        uint32_t Fh[4][4];
        const uint32_t base0 = sb + SM_F + (m0 + a_row) * APITCH + a_kadd;
#pragma unroll
        for (int ks = 0; ks < 4; ks++) ldsm_x4(Fh[ks], base0 + ks * 32);
#pragma unroll
        for (int ks = 0; ks < 4; ks++) {
            uint32_t bh[16];
#pragma unroll
            for (int g = 0; g < 4; g++)
                ldsm_x4(bh + 4 * g,
                        sb + SM_B2 + (g * 16 + b_row) * APITCH + ks * 32 + b_kadd);
#pragma unroll
            for (int nt = 0; nt < 8; nt++) {
                const uint32_t b0 = bh[(nt >> 1) * 4 + (nt & 1) * 2];
                const uint32_t b1v = bh[(nt >> 1) * 4 + (nt & 1) * 2 + 1];
                mma_f16(acc0[nt], Fh[ks], b0, b1v);
            }
        }
        const uint32_t base1 = base0 + 16 * APITCH;
#pragma unroll
        for (int ks = 0; ks < 4; ks++) ldsm_x4(Fh[ks], base1 + ks * 32);
#pragma unroll
        for (int ks = 0; ks < 4; ks++) {
            uint32_t bh[16];
#pragma unroll
            for (int g = 0; g < 4; g++)
                ldsm_x4(bh + 4 * g,
                        sb + SM_B2 + (g * 16 + b_row) * APITCH + ks * 32 + b_kadd);
#pragma unroll
            for (int nt = 0; nt < 8; nt++) {
                const uint32_t b0 = bh[(nt >> 1) * 4 + (nt & 1) * 2];
                const uint32_t b1v = bh[(nt >> 1) * 4 + (nt & 1) * 2 + 1];
                mma_f16(acc1[nt], Fh[ks], b0, b1v);
            }
        }
    }

    // ---- epilogue: ang = angular@Wa+ba on the fly, multiply, store ----
    const int gc = (lane & 3) * 2;
#pragma unroll
    for (int band = 0; band < 2; band++) {
        float (*ac)[4] = band ? acc1 : acc0;
#pragma unroll
        for (int rs = 0; rs < 2; rs++) {            // D frag: {0,1}=row r0, {2,3}=row r0+8
            const int m = m0 + band * 16 + rs * 8 + r0;
            float sa[16];
#pragma unroll
            for (int q = 0; q < 16; q++) sa[q] = sang[m * 17 + q];

            const size_t orow = (size_t)(n0 + m) * OUT_F;
#pragma unroll
            for (int nt = 0; nt < 8; nt++) {
                const int c0 = nt * 8 + gc;
                float a0 = sba_[c0], a1 = sba_[c0 + 1];
#pragma unroll
                for (int q = 0; q < 16; q++) {
                    a0 = fmaf(sa[q], sWa[q * 64 + c0], a0);
                    a1 = fmaf(sa[q], sWa[q * 64 + c0 + 1], a1);
                }
                float2 o;
                o.x = ac[nt][rs * 2 + 0] * a0;
                o.y = ac[nt][rs * 2 + 1] * a1;
                *(float2*)(out + orow + c0) = o;
            }
        }
    }
}

// ---------------------------------------------------------------------------
// Launch
// ---------------------------------------------------------------------------
extern "C" void kernel_launch(void* const* d_in, const int* in_sizes, int n_in,
                              void* d_out, int out_size)
{
    const float* features = (const float*)d_in[0];
    const float* radial   = (const float*)d_in[1];
    const float* angular  = (const float*)d_in[2];
    const float* W1       = (const float*)d_in[3];
    const float* b1       = (const float*)d_in[4];
    const float* W2       = (const float*)d_in[5];
    const float* b2       = (const float*)d_in[6];
    const float* Wa       = (const float*)d_in[7];
    const float* ba       = (const float*)d_in[8];
    float* out = (float*)d_out;
    (void)in_sizes; (void)n_in; (void)out_size;

    cudaFuncSetAttribute(tp_main, cudaFuncAttributeMaxDynamicSharedMemorySize, SMEM_BYTES);

    tp_wsplit<<<(64 * 4096 + 4096 + THREADS - 1) / THREADS, THREADS>>>(W2, b2);
    tp_main<<<NTILES, THREADS, SMEM_BYTES>>>(features, radial, angular,
                                             W1, b1, Wa, ba, out);
}